// round 9
// baseline (speedup 1.0000x reference)
#include <cuda_runtime.h>
#include <cuda_bf16.h>
#include <math.h>

// ---------------------------------------------------------------------------
// DiscriminativeLoss: B=4 batches, two losses:
//   binary:   pred [2, N], labels in [0,2)
//   instance: pred [5, N], labels in [0,6)
// out[0] = mean_b binary_loss, out[1] = mean_b instance_loss
//
// pass1: segment sums (register FMA accumulators) — at BW ceiling, unchanged.
// pass2: register-resident means + FSEL label-select (no in-loop LDS),
//        reverse iteration (L2 MRU), last-block finalize.
// ---------------------------------------------------------------------------

#define DELTA_V   0.5f
#define TWO_DD    6.0f
#define PREG      0.001f

// pass1: 4 blocks/SM, balanced by byte ratio 1:2
#define P1_NB_BIN   49
#define P1_NB_INST  99
#define P1_BLOCKS   (4 * (P1_NB_BIN + P1_NB_INST))   // 592

// pass2: 3 blocks/SM (reg-heavy FSEL tables), balanced 1:2
#define P2_NB_BIN   37
#define P2_NB_INST  74
#define P2_BLOCKS   (4 * (P2_NB_BIN + P2_NB_INST))   // 444

__device__ float    g_sum[2][4][8][8];   // [type][b][k][d]
__device__ float    g_cnt[2][4][8];      // [type][b][k]
__device__ float    g_var2[2][4];        // [type][b]
__device__ unsigned g_done;

__device__ __forceinline__ float fsqrt_approx(float x) {
    float r;
    asm("sqrt.approx.f32 %0, %1;" : "=f"(r) : "f"(x));
    return r;
}

struct Work { int type, b, xi, nblk; };
__device__ __forceinline__ Work map_block(int bid, int nb_bin, int nb_inst) {
    Work w;
    if (bid < nb_bin * 4) {
        w.type = 0; w.b = bid / nb_bin; w.xi = bid % nb_bin; w.nblk = nb_bin;
    } else {
        int j = bid - nb_bin * 4;
        w.type = 1; w.b = j / nb_inst; w.xi = j % nb_inst; w.nblk = nb_inst;
    }
    return w;
}

// ---------------------------------------------------------------------------
// Pass 1: segment sums + counts (unchanged — near BW ceiling)
// ---------------------------------------------------------------------------
template <int D, int K>
__device__ __forceinline__ void reduce_impl(const float* __restrict__ pred,
                                            const int* __restrict__ labels,
                                            int N, int xi, int nblk,
                                            float* __restrict__ gsum,
                                            float* __restrict__ gcnt) {
    float s[K * D];
    float c[K];
#pragma unroll
    for (int i = 0; i < K * D; i++) s[i] = 0.f;
#pragma unroll
    for (int k = 0; k < K; k++) c[k] = 0.f;

    const int n4 = N >> 2;
    const int4* lab4 = (const int4*)labels;
    const int stride = nblk * 256;

    for (int i = xi * 256 + threadIdx.x; i < n4; i += stride) {
        int4 L = lab4[i];
        float4 v[D];
#pragma unroll
        for (int d = 0; d < D; d++)
            v[d] = ((const float4*)(pred + (size_t)d * N))[i];

        int ls[4] = {L.x, L.y, L.z, L.w};
#pragma unroll
        for (int e = 0; e < 4; e++) {
            int lab = ls[e];
#pragma unroll
            for (int k = 0; k < K; k++) {
                float m = (lab == k) ? 1.f : 0.f;
                c[k] += m;
#pragma unroll
                for (int d = 0; d < D; d++) {
                    float val = (e == 0) ? v[d].x : (e == 1) ? v[d].y
                               : (e == 2) ? v[d].z : v[d].w;
                    s[k * D + d] += m * val;
                }
            }
        }
    }

#pragma unroll
    for (int o = 16; o > 0; o >>= 1) {
#pragma unroll
        for (int i = 0; i < K * D; i++) s[i] += __shfl_xor_sync(0xffffffffu, s[i], o);
#pragma unroll
        for (int k = 0; k < K; k++) c[k] += __shfl_xor_sync(0xffffffffu, c[k], o);
    }

    __shared__ float sh[K * D + K];
    for (int i = threadIdx.x; i < K * D + K; i += blockDim.x) sh[i] = 0.f;
    __syncthreads();
    if ((threadIdx.x & 31) == 0) {
#pragma unroll
        for (int i = 0; i < K * D; i++) atomicAdd(&sh[i], s[i]);
#pragma unroll
        for (int k = 0; k < K; k++) atomicAdd(&sh[K * D + k], c[k]);
    }
    __syncthreads();
    if (threadIdx.x < K * D) {
        int k = threadIdx.x / D, d = threadIdx.x % D;
        atomicAdd(&gsum[k * 8 + d], sh[threadIdx.x]);
    }
    if (threadIdx.x < K) atomicAdd(&gcnt[threadIdx.x], sh[K * D + threadIdx.x]);
}

__global__ __launch_bounds__(256, 4) void pass1_kernel(
    const float* __restrict__ binL, const int* __restrict__ binLab,
    const float* __restrict__ instL, const int* __restrict__ instLab, int N) {
    Work w = map_block(blockIdx.x, P1_NB_BIN, P1_NB_INST);
    if (w.type == 0) {
        reduce_impl<2, 2>(binL + (size_t)w.b * 2 * N, binLab + (size_t)w.b * N,
                          N, w.xi, w.nblk, &g_sum[0][w.b][0][0], &g_cnt[0][w.b][0]);
    } else {
        reduce_impl<5, 6>(instL + (size_t)w.b * 5 * N, instLab + (size_t)w.b * N,
                          N, w.xi, w.nblk, &g_sum[1][w.b][0][0], &g_cnt[1][w.b][0]);
    }
}

// ---------------------------------------------------------------------------
// Pass 2 binary: register means, FSEL select, reverse iteration.
// ---------------------------------------------------------------------------
__device__ __forceinline__ void var_bin(const float* __restrict__ pred,
                                        const int* __restrict__ labels,
                                        int N, int xi, int nblk,
                                        const float* __restrict__ gsum,
                                        const float* __restrict__ gcnt,
                                        float* __restrict__ gvar) {
    float i0 = 1.f / gcnt[0], i1 = 1.f / gcnt[1];
    float m00 = gsum[0] * i0, m01 = gsum[1] * i0;
    float m10 = gsum[8] * i1, m11 = gsum[9] * i1;

    float acc = 0.f;
    const int n4 = N >> 2;
    const int4* lab4 = (const int4*)labels;
    const int stride = nblk * 256;
    const int first = xi * 256 + threadIdx.x;

    if (first < n4) {
        int count = (n4 - first + stride - 1) / stride;
        int i = first + (count - 1) * stride;      // reverse: MRU first
        for (; i >= first; i -= stride) {
            int4 L = lab4[i];
            float4 v0 = ((const float4*)pred)[i];
            float4 v1 = ((const float4*)(pred + (size_t)N))[i];

            int ls[4] = {L.x, L.y, L.z, L.w};
#pragma unroll
            for (int e = 0; e < 4; e++) {
                bool p = (ls[e] != 0);
                float mu0 = p ? m10 : m00;
                float mu1 = p ? m11 : m01;
                float w   = p ? i1  : i0;
                float x0 = (e == 0) ? v0.x : (e == 1) ? v0.y
                          : (e == 2) ? v0.z : v0.w;
                float x1 = (e == 0) ? v1.x : (e == 1) ? v1.y
                          : (e == 2) ? v1.z : v1.w;
                float d0 = mu0 - x0, d1 = mu1 - x1;
                float dist = fsqrt_approx(d0 * d0 + d1 * d1);
                float h = fmaxf(dist - DELTA_V, 0.f);
                acc += h * h * w;
            }
        }
    }

#pragma unroll
    for (int o = 16; o > 0; o >>= 1)
        acc += __shfl_xor_sync(0xffffffffu, acc, o);

    __shared__ float shv;
    if (threadIdx.x == 0) shv = 0.f;
    __syncthreads();
    if ((threadIdx.x & 31) == 0) atomicAdd(&shv, acc);
    __syncthreads();
    if (threadIdx.x == 0) atomicAdd(gvar, shv);
}

// ---------------------------------------------------------------------------
// Pass 2 instance: 36 register-resident values, FSEL chains, reverse iter.
// ---------------------------------------------------------------------------
__device__ __forceinline__ void var_inst(const float* __restrict__ pred,
                                         const int* __restrict__ labels,
                                         int N, int xi, int nblk,
                                         const float* __restrict__ gsum,
                                         const float* __restrict__ gcnt,
                                         float* __restrict__ gvar) {
    float M[6][5], W[6];
#pragma unroll
    for (int k = 0; k < 6; k++) {
        float inv = 1.f / gcnt[k];
        W[k] = inv;
#pragma unroll
        for (int d = 0; d < 5; d++)
            M[k][d] = gsum[k * 8 + d] * inv;
    }

    float acc = 0.f;
    const int n4 = N >> 2;
    const int4* lab4 = (const int4*)labels;
    const int stride = nblk * 256;
    const int first = xi * 256 + threadIdx.x;

    if (first < n4) {
        int count = (n4 - first + stride - 1) / stride;
        int i = first + (count - 1) * stride;      // reverse: MRU first
        for (; i >= first; i -= stride) {
            int4 L = lab4[i];
            float4 v[5];
#pragma unroll
            for (int d = 0; d < 5; d++)
                v[d] = ((const float4*)(pred + (size_t)d * N))[i];

            int ls[4] = {L.x, L.y, L.z, L.w};
#pragma unroll
            for (int e = 0; e < 4; e++) {
                int lab = ls[e];
                float mu0 = M[0][0], mu1 = M[0][1], mu2 = M[0][2];
                float mu3 = M[0][3], mu4 = M[0][4], w = W[0];
#pragma unroll
                for (int k = 1; k < 6; k++) {
                    bool p = (lab == k);
                    mu0 = p ? M[k][0] : mu0;
                    mu1 = p ? M[k][1] : mu1;
                    mu2 = p ? M[k][2] : mu2;
                    mu3 = p ? M[k][3] : mu3;
                    mu4 = p ? M[k][4] : mu4;
                    w   = p ? W[k]    : w;
                }
                float x0 = (e == 0) ? v[0].x : (e == 1) ? v[0].y
                          : (e == 2) ? v[0].z : v[0].w;
                float x1 = (e == 0) ? v[1].x : (e == 1) ? v[1].y
                          : (e == 2) ? v[1].z : v[1].w;
                float x2 = (e == 0) ? v[2].x : (e == 1) ? v[2].y
                          : (e == 2) ? v[2].z : v[2].w;
                float x3 = (e == 0) ? v[3].x : (e == 1) ? v[3].y
                          : (e == 2) ? v[3].z : v[3].w;
                float x4 = (e == 0) ? v[4].x : (e == 1) ? v[4].y
                          : (e == 2) ? v[4].z : v[4].w;
                float d0 = mu0 - x0, d1 = mu1 - x1, d2 = mu2 - x2;
                float d3 = mu3 - x3, d4 = mu4 - x4;
                float sq = d0 * d0 + d1 * d1 + d2 * d2 + d3 * d3 + d4 * d4;
                float dist = fsqrt_approx(sq);
                float h = fmaxf(dist - DELTA_V, 0.f);
                acc += h * h * w;
            }
        }
    }

#pragma unroll
    for (int o = 16; o > 0; o >>= 1)
        acc += __shfl_xor_sync(0xffffffffu, acc, o);

    __shared__ float shv;
    if (threadIdx.x == 0) shv = 0.f;
    __syncthreads();
    if ((threadIdx.x & 31) == 0) atomicAdd(&shv, acc);
    __syncthreads();
    if (threadIdx.x == 0) atomicAdd(gvar, shv);
}

__global__ __launch_bounds__(256, 3) void pass2_kernel(
    const float* __restrict__ binL, const int* __restrict__ binLab,
    const float* __restrict__ instL, const int* __restrict__ instLab, int N,
    float* __restrict__ out) {
    Work w = map_block(blockIdx.x, P2_NB_BIN, P2_NB_INST);
    if (w.type == 0) {
        var_bin(binL + (size_t)w.b * 2 * N, binLab + (size_t)w.b * N,
                N, w.xi, w.nblk, &g_sum[0][w.b][0][0], &g_cnt[0][w.b][0],
                &g_var2[0][w.b]);
    } else {
        var_inst(instL + (size_t)w.b * 5 * N, instLab + (size_t)w.b * N,
                 N, w.xi, w.nblk, &g_sum[1][w.b][0][0], &g_cnt[1][w.b][0],
                 &g_var2[1][w.b]);
    }

    // ---- last-block finalize ----
    __threadfence();
    __syncthreads();
    __shared__ bool is_last;
    if (threadIdx.x == 0) {
        unsigned v = atomicAdd(&g_done, 1u);
        is_last = (v == (unsigned)(P2_BLOCKS - 1));
    }
    __syncthreads();
    if (!is_last) return;
    __threadfence();

    __shared__ float s_res[2];
    if (threadIdx.x < 8) {
        int type = threadIdx.x >> 2, b2 = threadIdx.x & 3;
        int K = type ? 6 : 2, D = type ? 5 : 2;

        float m[6][5];
        for (int k = 0; k < K; k++) {
            float cnt = g_cnt[type][b2][k];
            for (int d = 0; d < D; d++)
                m[k][d] = g_sum[type][b2][k][d] / cnt;
        }
        float l_var = g_var2[type][b2] / (float)K;

        float ld = 0.f;
        for (int i = 0; i < K; i++)
            for (int j = 0; j < K; j++) {
                if (i == j) continue;
                float sq = 0.f;
                for (int d = 0; d < D; d++) {
                    float df = m[i][d] - m[j][d];
                    sq += df * df;
                }
                float dn = fmaxf(TWO_DD - sqrtf(sq), 0.f);
                ld += dn * dn;
            }
        ld /= (float)(K * (K - 1));

        float lr = 0.f;
        for (int k = 0; k < K; k++) {
            float sq = 0.f;
            for (int d = 0; d < D; d++) sq += m[k][d] * m[k][d];
            lr += sqrtf(sq);
        }
        lr /= (float)K;

        float loss = l_var + ld + PREG * lr;
        loss += __shfl_xor_sync(0x000000ffu, loss, 1);
        loss += __shfl_xor_sync(0x000000ffu, loss, 2);
        if ((threadIdx.x & 3) == 0) s_res[type] = loss * 0.25f;
    }
    __syncthreads();
    if (threadIdx.x == 0) {
        out[0] = s_res[0];
        out[1] = s_res[1];
        g_done = 0;
    }
    // re-zero accumulators for the next graph replay
    float* p1 = &g_sum[0][0][0][0];
    for (int i = threadIdx.x; i < 2 * 4 * 8 * 8; i += blockDim.x) p1[i] = 0.f;
    float* p2 = &g_cnt[0][0][0];
    for (int i = threadIdx.x; i < 2 * 4 * 8; i += blockDim.x) p2[i] = 0.f;
    float* p3 = &g_var2[0][0];
    for (int i = threadIdx.x; i < 2 * 4; i += blockDim.x) p3[i] = 0.f;
}

// ---------------------------------------------------------------------------
extern "C" void kernel_launch(void* const* d_in, const int* in_sizes, int n_in,
                              void* d_out, int out_size) {
    const float* binL    = (const float*)d_in[0];
    const int*   binLab  = (const int*)d_in[1];
    const float* instL   = (const float*)d_in[2];
    const int*   instLab = (const int*)d_in[3];
    float* out = (float*)d_out;

    int N = in_sizes[1] / 4;  // B = 4 batches

    pass1_kernel<<<P1_BLOCKS, 256>>>(binL, binLab, instL, instLab, N);
    pass2_kernel<<<P2_BLOCKS, 256>>>(binL, binLab, instL, instLab, N, out);
}

// round 13
// speedup vs baseline: 1.1088x; 1.1088x over previous
#include <cuda_runtime.h>
#include <cuda_bf16.h>
#include <math.h>

// ---------------------------------------------------------------------------
// DiscriminativeLoss: B=4 batches, two losses:
//   binary:   pred [2, N], labels in [0,2)
//   instance: pred [5, N], labels in [0,6)
// out[0] = mean_b binary_loss, out[1] = mean_b instance_loss
//
// R6 structure (best: 35.6us) + L2 evict-last via createpolicy/cache_hint on
// all streaming loads so pass2 is served from L2, not DRAM.
// ---------------------------------------------------------------------------

#define DELTA_V   0.5f
#define TWO_DD    6.0f
#define PREG      0.001f

// pass1: 4 blocks/SM, balanced by byte ratio 1:2
#define P1_NB_BIN   49
#define P1_NB_INST  99
#define P1_BLOCKS   (4 * (P1_NB_BIN + P1_NB_INST))   // 592

// pass2: 6 blocks/SM (lean), balanced 1:2
#define P2_NB_BIN   74
#define P2_NB_INST  148
#define P2_BLOCKS   (4 * (P2_NB_BIN + P2_NB_INST))   // 888

__device__ float    g_sum[2][4][8][8];   // [type][b][k][d]
__device__ float    g_cnt[2][4][8];      // [type][b][k]
__device__ float    g_var2[2][4];        // [type][b]
__device__ unsigned g_done;

__device__ __forceinline__ float fsqrt_approx(float x) {
    float r;
    asm("sqrt.approx.f32 %0, %1;" : "=f"(r) : "f"(x));
    return r;
}

// L2 evict-last policy + hinted 128-bit loads
__device__ __forceinline__ unsigned long long mk_evict_last_policy() {
    unsigned long long p;
    asm("createpolicy.fractional.L2::evict_last.b64 %0, 1.0;" : "=l"(p));
    return p;
}
__device__ __forceinline__ float4 ldg_el_f4(const float4* p, unsigned long long pol) {
    float4 r;
    asm("ld.global.nc.L2::cache_hint.v4.f32 {%0,%1,%2,%3}, [%4], %5;"
        : "=f"(r.x), "=f"(r.y), "=f"(r.z), "=f"(r.w) : "l"(p), "l"(pol));
    return r;
}
__device__ __forceinline__ int4 ldg_el_i4(const int4* p, unsigned long long pol) {
    int4 r;
    asm("ld.global.nc.L2::cache_hint.v4.u32 {%0,%1,%2,%3}, [%4], %5;"
        : "=r"(r.x), "=r"(r.y), "=r"(r.z), "=r"(r.w) : "l"(p), "l"(pol));
    return r;
}

struct Work { int type, b, xi, nblk; };
__device__ __forceinline__ Work map_block(int bid, int nb_bin, int nb_inst) {
    Work w;
    if (bid < nb_bin * 4) {
        w.type = 0; w.b = bid / nb_bin; w.xi = bid % nb_bin; w.nblk = nb_bin;
    } else {
        int j = bid - nb_bin * 4;
        w.type = 1; w.b = j / nb_inst; w.xi = j % nb_inst; w.nblk = nb_inst;
    }
    return w;
}

// ---------------------------------------------------------------------------
// Pass 1: segment sums + counts
// ---------------------------------------------------------------------------
template <int D, int K>
__device__ __forceinline__ void reduce_impl(const float* __restrict__ pred,
                                            const int* __restrict__ labels,
                                            int N, int xi, int nblk,
                                            float* __restrict__ gsum,
                                            float* __restrict__ gcnt) {
    const unsigned long long pol = mk_evict_last_policy();
    float s[K * D];
    float c[K];
#pragma unroll
    for (int i = 0; i < K * D; i++) s[i] = 0.f;
#pragma unroll
    for (int k = 0; k < K; k++) c[k] = 0.f;

    const int n4 = N >> 2;
    const int4* lab4 = (const int4*)labels;
    const int stride = nblk * 256;

    for (int i = xi * 256 + threadIdx.x; i < n4; i += stride) {
        int4 L = ldg_el_i4(lab4 + i, pol);
        float4 v[D];
#pragma unroll
        for (int d = 0; d < D; d++)
            v[d] = ldg_el_f4((const float4*)(pred + (size_t)d * N) + i, pol);

        int ls[4] = {L.x, L.y, L.z, L.w};
#pragma unroll
        for (int e = 0; e < 4; e++) {
            int lab = ls[e];
#pragma unroll
            for (int k = 0; k < K; k++) {
                float m = (lab == k) ? 1.f : 0.f;
                c[k] += m;
#pragma unroll
                for (int d = 0; d < D; d++) {
                    float val = (e == 0) ? v[d].x : (e == 1) ? v[d].y
                               : (e == 2) ? v[d].z : v[d].w;
                    s[k * D + d] += m * val;
                }
            }
        }
    }

#pragma unroll
    for (int o = 16; o > 0; o >>= 1) {
#pragma unroll
        for (int i = 0; i < K * D; i++) s[i] += __shfl_xor_sync(0xffffffffu, s[i], o);
#pragma unroll
        for (int k = 0; k < K; k++) c[k] += __shfl_xor_sync(0xffffffffu, c[k], o);
    }

    __shared__ float sh[K * D + K];
    for (int i = threadIdx.x; i < K * D + K; i += blockDim.x) sh[i] = 0.f;
    __syncthreads();
    if ((threadIdx.x & 31) == 0) {
#pragma unroll
        for (int i = 0; i < K * D; i++) atomicAdd(&sh[i], s[i]);
#pragma unroll
        for (int k = 0; k < K; k++) atomicAdd(&sh[K * D + k], c[k]);
    }
    __syncthreads();
    if (threadIdx.x < K * D) {
        int k = threadIdx.x / D, d = threadIdx.x % D;
        atomicAdd(&gsum[k * 8 + d], sh[threadIdx.x]);
    }
    if (threadIdx.x < K) atomicAdd(&gcnt[threadIdx.x], sh[K * D + threadIdx.x]);
}

__global__ __launch_bounds__(256, 4) void pass1_kernel(
    const float* __restrict__ binL, const int* __restrict__ binLab,
    const float* __restrict__ instL, const int* __restrict__ instLab, int N) {
    Work w = map_block(blockIdx.x, P1_NB_BIN, P1_NB_INST);
    if (w.type == 0) {
        reduce_impl<2, 2>(binL + (size_t)w.b * 2 * N, binLab + (size_t)w.b * N,
                          N, w.xi, w.nblk, &g_sum[0][w.b][0][0], &g_cnt[0][w.b][0]);
    } else {
        reduce_impl<5, 6>(instL + (size_t)w.b * 5 * N, instLab + (size_t)w.b * N,
                          N, w.xi, w.nblk, &g_sum[1][w.b][0][0], &g_cnt[1][w.b][0]);
    }
}

// ---------------------------------------------------------------------------
// Pass 2: scalar smem means (R6 form), hinted loads, single accumulator.
// ---------------------------------------------------------------------------
template <int D, int K, int UNROLL>
__device__ __forceinline__ void var_impl(const float* __restrict__ pred,
                                         const int* __restrict__ labels,
                                         int N, int xi, int nblk,
                                         const float* __restrict__ gsum,
                                         const float* __restrict__ gcnt,
                                         float* __restrict__ gvar) {
    const unsigned long long pol = mk_evict_last_policy();
    __shared__ float sm[K * D];
    __shared__ float sinv[K];
    if (threadIdx.x < K * D) {
        int k = threadIdx.x / D, d = threadIdx.x % D;
        sm[threadIdx.x] = gsum[k * 8 + d] / gcnt[k];
    }
    if (threadIdx.x < K) sinv[threadIdx.x] = 1.f / gcnt[threadIdx.x];
    __syncthreads();

    float acc = 0.f;

    const int n4 = N >> 2;
    const int4* lab4 = (const int4*)labels;
    const int stride = nblk * 256;

#pragma unroll UNROLL
    for (int i = xi * 256 + threadIdx.x; i < n4; i += stride) {
        int4 L = ldg_el_i4(lab4 + i, pol);
        float4 v[D];
#pragma unroll
        for (int d = 0; d < D; d++)
            v[d] = ldg_el_f4((const float4*)(pred + (size_t)d * N) + i, pol);

        int ls[4] = {L.x, L.y, L.z, L.w};
#pragma unroll
        for (int e = 0; e < 4; e++) {
            int lab = ls[e];
            float sq = 0.f;
#pragma unroll
            for (int d = 0; d < D; d++) {
                float val = (e == 0) ? v[d].x : (e == 1) ? v[d].y
                           : (e == 2) ? v[d].z : v[d].w;
                float df = sm[lab * D + d] - val;
                sq += df * df;
            }
            float dist = fsqrt_approx(sq);
            float h = fmaxf(dist - DELTA_V, 0.f);
            acc += h * h * sinv[lab];
        }
    }

#pragma unroll
    for (int o = 16; o > 0; o >>= 1)
        acc += __shfl_xor_sync(0xffffffffu, acc, o);

    __shared__ float shv;
    if (threadIdx.x == 0) shv = 0.f;
    __syncthreads();
    if ((threadIdx.x & 31) == 0) atomicAdd(&shv, acc);
    __syncthreads();
    if (threadIdx.x == 0) atomicAdd(gvar, shv);
}

__global__ __launch_bounds__(256, 6) void pass2_kernel(
    const float* __restrict__ binL, const int* __restrict__ binLab,
    const float* __restrict__ instL, const int* __restrict__ instLab, int N,
    float* __restrict__ out) {
    Work w = map_block(blockIdx.x, P2_NB_BIN, P2_NB_INST);
    if (w.type == 0) {
        var_impl<2, 2, 2>(binL + (size_t)w.b * 2 * N, binLab + (size_t)w.b * N,
                          N, w.xi, w.nblk, &g_sum[0][w.b][0][0], &g_cnt[0][w.b][0],
                          &g_var2[0][w.b]);
    } else {
        var_impl<5, 6, 1>(instL + (size_t)w.b * 5 * N, instLab + (size_t)w.b * N,
                          N, w.xi, w.nblk, &g_sum[1][w.b][0][0], &g_cnt[1][w.b][0],
                          &g_var2[1][w.b]);
    }

    // ---- last-block finalize ----
    __threadfence();
    __syncthreads();
    __shared__ bool is_last;
    if (threadIdx.x == 0) {
        unsigned v = atomicAdd(&g_done, 1u);
        is_last = (v == (unsigned)(P2_BLOCKS - 1));
    }
    __syncthreads();
    if (!is_last) return;
    __threadfence();

    __shared__ float s_res[2];
    if (threadIdx.x < 8) {
        int type = threadIdx.x >> 2, b2 = threadIdx.x & 3;
        int K = type ? 6 : 2, D = type ? 5 : 2;

        float m[6][5];
        for (int k = 0; k < K; k++) {
            float cnt = g_cnt[type][b2][k];
            for (int d = 0; d < D; d++)
                m[k][d] = g_sum[type][b2][k][d] / cnt;
        }
        float l_var = g_var2[type][b2] / (float)K;

        float ld = 0.f;
        for (int i = 0; i < K; i++)
            for (int j = 0; j < K; j++) {
                if (i == j) continue;
                float sq = 0.f;
                for (int d = 0; d < D; d++) {
                    float df = m[i][d] - m[j][d];
                    sq += df * df;
                }
                float dn = fmaxf(TWO_DD - sqrtf(sq), 0.f);
                ld += dn * dn;
            }
        ld /= (float)(K * (K - 1));

        float lr = 0.f;
        for (int k = 0; k < K; k++) {
            float sq = 0.f;
            for (int d = 0; d < D; d++) sq += m[k][d] * m[k][d];
            lr += sqrtf(sq);
        }
        lr /= (float)K;

        float loss = l_var + ld + PREG * lr;
        loss += __shfl_xor_sync(0x000000ffu, loss, 1);
        loss += __shfl_xor_sync(0x000000ffu, loss, 2);
        if ((threadIdx.x & 3) == 0) s_res[type] = loss * 0.25f;
    }
    __syncthreads();
    if (threadIdx.x == 0) {
        out[0] = s_res[0];
        out[1] = s_res[1];
        g_done = 0;
    }
    // re-zero accumulators for the next graph replay
    float* p1 = &g_sum[0][0][0][0];
    for (int i = threadIdx.x; i < 2 * 4 * 8 * 8; i += blockDim.x) p1[i] = 0.f;
    float* p2 = &g_cnt[0][0][0];
    for (int i = threadIdx.x; i < 2 * 4 * 8; i += blockDim.x) p2[i] = 0.f;
    float* p3 = &g_var2[0][0];
    for (int i = threadIdx.x; i < 2 * 4; i += blockDim.x) p3[i] = 0.f;
}

// ---------------------------------------------------------------------------
extern "C" void kernel_launch(void* const* d_in, const int* in_sizes, int n_in,
                              void* d_out, int out_size) {
    const float* binL    = (const float*)d_in[0];
    const int*   binLab  = (const int*)d_in[1];
    const float* instL   = (const float*)d_in[2];
    const int*   instLab = (const int*)d_in[3];
    float* out = (float*)d_out;

    int N = in_sizes[1] / 4;  // B = 4 batches

    pass1_kernel<<<P1_BLOCKS, 256>>>(binL, binLab, instL, instLab, N);
    pass2_kernel<<<P2_BLOCKS, 256>>>(binL, binLab, instL, instLab, N, out);
}